// round 1
// baseline (speedup 1.0000x reference)
#include <cuda_runtime.h>
#include <cstdint>

#define CIN 256
#define COUT 256
#define HH 56
#define WW 56
#define NN 8
#define KKER 9
#define HWSZ (HH*WW)            // 3136
#define M_TOTAL (NN*HWSZ)       // 25088
#define KD (KKER*CIN)           // 2304

// Scratch (device globals — no runtime allocation allowed)
__device__ float g_xnhwc[(size_t)NN*HWSZ*CIN];      // 25.7 MB
__device__ float g_V[(size_t)M_TOTAL*KD];           // 231 MB
__device__ float g_B[(size_t)KD*COUT];              // 2.36 MB

// ---------------------------------------------------------------------------
// Kernel 1: NCHW -> NHWC transpose (per image: 256 x 3136 -> 3136 x 256)
// ---------------------------------------------------------------------------
__global__ void k_transpose(const float* __restrict__ x) {
    __shared__ float t[32][33];
    int n   = blockIdx.z;
    int hw0 = blockIdx.x * 32;   // 3136/32 = 98
    int c0  = blockIdx.y * 32;   // 256/32 = 8
    int tx = threadIdx.x, ty = threadIdx.y;  // 32 x 8
    const float* xin = x + (size_t)n * CIN * HWSZ;
    #pragma unroll
    for (int i = 0; i < 4; i++) {
        int c = c0 + ty + i * 8;
        t[ty + i * 8][tx] = xin[(size_t)c * HWSZ + hw0 + tx];
    }
    __syncthreads();
    float* xo = g_xnhwc + (size_t)n * HWSZ * CIN;
    #pragma unroll
    for (int i = 0; i < 4; i++) {
        int hw = hw0 + ty + i * 8;
        xo[(size_t)hw * CIN + c0 + tx] = t[tx][ty + i * 8];
    }
}

// ---------------------------------------------------------------------------
// Kernel 2: weight transpose  B[k*256+ci][co] = weight[co][ci][k]
// ---------------------------------------------------------------------------
__global__ void k_wt(const float* __restrict__ w) {
    int idx = blockIdx.x * 256 + threadIdx.x;   // KD*COUT = 589824
    int co = idx & 255;
    int r  = idx >> 8;        // k*256 + ci
    int ci = r & 255;
    int k  = r >> 8;
    g_B[idx] = w[((size_t)co * CIN + ci) * KKER + k];
}

// ---------------------------------------------------------------------------
// Kernel 3: bilinear gather + modulation -> V[m][k*256+c]
// one block per output pixel, thread = channel
// ---------------------------------------------------------------------------
__global__ __launch_bounds__(256) void k_gather(const float* __restrict__ offset,
                                                const float* __restrict__ mask) {
    int pix = blockIdx.x;
    int c   = threadIdx.x;
    int n   = pix / HWSZ;
    int hw  = pix % HWSZ;
    int ho  = hw / WW, wo = hw % WW;
    const float* xb = g_xnhwc + (size_t)n * HWSZ * CIN;
    float* vout = g_V + (size_t)pix * KD;

    #pragma unroll
    for (int k = 0; k < KKER; k++) {
        float dy = offset[((size_t)n * 18 + 2 * k)     * HWSZ + hw];
        float dx = offset[((size_t)n * 18 + 2 * k + 1) * HWSZ + hw];
        float mm = mask  [((size_t)n * KKER + k)       * HWSZ + hw];
        float py = dy + (float)(k / 3) + (float)(ho - 1);
        float px = dx + (float)(k % 3) + (float)(wo - 1);
        float fy = floorf(py), fx = floorf(px);
        int y0 = (int)fy, x0 = (int)fx;
        float wy1 = py - fy, wx1 = px - fx;
        float wy0 = 1.0f - wy1, wx0 = 1.0f - wx1;

        float acc = 0.0f;
        {
            int y = y0, x = x0;
            if (y >= 0 && y < HH && x >= 0 && x < WW)
                acc += (wy0 * wx0) * xb[(size_t)(y * WW + x) * CIN + c];
        }
        {
            int y = y0, x = x0 + 1;
            if (y >= 0 && y < HH && x >= 0 && x < WW)
                acc += (wy0 * wx1) * xb[(size_t)(y * WW + x) * CIN + c];
        }
        {
            int y = y0 + 1, x = x0;
            if (y >= 0 && y < HH && x >= 0 && x < WW)
                acc += (wy1 * wx0) * xb[(size_t)(y * WW + x) * CIN + c];
        }
        {
            int y = y0 + 1, x = x0 + 1;
            if (y >= 0 && y < HH && x >= 0 && x < WW)
                acc += (wy1 * wx1) * xb[(size_t)(y * WW + x) * CIN + c];
        }
        vout[k * CIN + c] = acc * mm;
    }
}

// ---------------------------------------------------------------------------
// Kernel 4: GEMM  C[M=25088, N=256] = V[M, 2304] * B[2304, 256]  (+bias)
// packed fp32x2 FMA (FFMA2), pairs over adjacent M rows.
// BM=128, BN=64, BK=16, 256 threads, thread tile 8M x 4N.
// ---------------------------------------------------------------------------
__device__ __forceinline__ unsigned long long fma2(unsigned long long a,
                                                   unsigned long long b,
                                                   unsigned long long c) {
    unsigned long long d;
    asm("fma.rn.f32x2 %0, %1, %2, %3;" : "=l"(d) : "l"(a), "l"(b), "l"(c));
    return d;
}
__device__ __forceinline__ unsigned long long dup2(float v) {
    unsigned long long d;
    unsigned u = __float_as_uint(v);
    asm("mov.b64 %0, {%1, %1};" : "=l"(d) : "r"(u));
    return d;
}
__device__ __forceinline__ float f2lo(unsigned long long a) {
    return __uint_as_float((unsigned)(a & 0xffffffffULL));
}
__device__ __forceinline__ float f2hi(unsigned long long a) {
    return __uint_as_float((unsigned)(a >> 32));
}

#define BM 128
#define BN 64
#define BK 16

__global__ __launch_bounds__(256) void k_gemm(const float* __restrict__ bias,
                                              float* __restrict__ out) {
    __shared__ float As[BK][BM + 4];   // k-major, padded (2-way max on store)
    __shared__ float Bs[BK][BN];

    int ntile = blockIdx.x;   // 0..3   (x fastest so 4 CTAs share the A tile in L2)
    int mtile = blockIdx.y;   // 0..195
    int tid = threadIdx.x;
    int tx = tid & 15;        // N direction: 16 threads x 4 cols
    int ty = tid >> 4;        // M direction: 16 threads x 8 rows
    int m0 = mtile * BM;
    int n0 = ntile * BN;

    unsigned long long acc[4][4];     // [m-pair][n]
    #pragma unroll
    for (int i = 0; i < 4; i++)
        #pragma unroll
        for (int j = 0; j < 4; j++) acc[i][j] = 0ULL;

    const float* Ag = g_V + (size_t)m0 * KD;
    const float* Bg = g_B + n0;

    for (int kt = 0; kt < KD; kt += BK) {
        // load A tile: 128x16 = 2048 elems, 8 per thread
        #pragma unroll
        for (int i = 0; i < 8; i++) {
            int idx = tid + i * 256;
            int row = idx >> 4;
            int col = idx & 15;
            As[col][row] = Ag[(size_t)row * KD + kt + col];
        }
        // load B tile: 16x64 = 1024 elems, 4 per thread
        #pragma unroll
        for (int i = 0; i < 4; i++) {
            int idx = tid + i * 256;
            int row = idx >> 6;
            int col = idx & 63;
            Bs[row][col] = Bg[(size_t)(kt + row) * COUT + col];
        }
        __syncthreads();

        #pragma unroll
        for (int k = 0; k < BK; k++) {
            const float* ap = &As[k][ty * 8];
            ulonglong2 aA = *reinterpret_cast<const ulonglong2*>(ap);      // m pairs 0,1
            ulonglong2 aB = *reinterpret_cast<const ulonglong2*>(ap + 4);  // m pairs 2,3
            float4 bv = *reinterpret_cast<const float4*>(&Bs[k][tx * 4]);
            unsigned long long b0 = dup2(bv.x), b1 = dup2(bv.y),
                               b2 = dup2(bv.z), b3 = dup2(bv.w);
            acc[0][0] = fma2(aA.x, b0, acc[0][0]);
            acc[0][1] = fma2(aA.x, b1, acc[0][1]);
            acc[0][2] = fma2(aA.x, b2, acc[0][2]);
            acc[0][3] = fma2(aA.x, b3, acc[0][3]);
            acc[1][0] = fma2(aA.y, b0, acc[1][0]);
            acc[1][1] = fma2(aA.y, b1, acc[1][1]);
            acc[1][2] = fma2(aA.y, b2, acc[1][2]);
            acc[1][3] = fma2(aA.y, b3, acc[1][3]);
            acc[2][0] = fma2(aB.x, b0, acc[2][0]);
            acc[2][1] = fma2(aB.x, b1, acc[2][1]);
            acc[2][2] = fma2(aB.x, b2, acc[2][2]);
            acc[2][3] = fma2(aB.x, b3, acc[2][3]);
            acc[3][0] = fma2(aB.y, b0, acc[3][0]);
            acc[3][1] = fma2(aB.y, b1, acc[3][1]);
            acc[3][2] = fma2(aB.y, b2, acc[3][2]);
            acc[3][3] = fma2(aB.y, b3, acc[3][3]);
        }
        __syncthreads();
    }

    // epilogue: thread's 8 M-rows lie in one image (3136 % 8 == 0, ty*8 aligned)
    int m = m0 + ty * 8;
    int n_img = m / HWSZ;
    int hw = m % HWSZ;
    #pragma unroll
    for (int j = 0; j < 4; j++) {
        int co = n0 + tx * 4 + j;
        float bv = bias[co];
        float4 v0, v1;
        v0.x = f2lo(acc[0][j]) + bv;
        v0.y = f2hi(acc[0][j]) + bv;
        v0.z = f2lo(acc[1][j]) + bv;
        v0.w = f2hi(acc[1][j]) + bv;
        v1.x = f2lo(acc[2][j]) + bv;
        v1.y = f2hi(acc[2][j]) + bv;
        v1.z = f2lo(acc[3][j]) + bv;
        v1.w = f2hi(acc[3][j]) + bv;
        float* op = out + ((size_t)n_img * COUT + co) * HWSZ + hw;
        *reinterpret_cast<float4*>(op)     = v0;
        *reinterpret_cast<float4*>(op + 4) = v1;
    }
}

// ---------------------------------------------------------------------------
// Launch
// inputs: 0=x (8,256,56,56), 1=offset (8,18,56,56), 2=mask (8,9,56,56),
//         3=weight (256,256,3,3), 4=bias (256)
// output: (8,256,56,56) fp32
// ---------------------------------------------------------------------------
extern "C" void kernel_launch(void* const* d_in, const int* in_sizes, int n_in,
                              void* d_out, int out_size) {
    const float* x      = (const float*)d_in[0];
    const float* offset = (const float*)d_in[1];
    const float* mask   = (const float*)d_in[2];
    const float* weight = (const float*)d_in[3];
    const float* bias   = (const float*)d_in[4];
    float* out = (float*)d_out;

    {
        dim3 grid(HWSZ / 32, CIN / 32, NN);   // 98, 8, 8
        dim3 block(32, 8);
        k_transpose<<<grid, block>>>(x);
    }
    {
        k_wt<<<KD, 256>>>(weight);            // 2304 blocks
    }
    {
        k_gather<<<M_TOTAL, 256>>>(offset, mask);
    }
    {
        dim3 grid(COUT / BN, M_TOTAL / BM);   // 4 x 196
        k_gemm<<<grid, 256>>>(bias, out);
    }
}

// round 3
// speedup vs baseline: 1.8635x; 1.8635x over previous
#include <cuda_runtime.h>
#include <cuda_bf16.h>
#include <cstdint>

#define CIN 256
#define COUT 256
#define HH 56
#define WW 56
#define NN 8
#define KKER 9
#define HWSZ (HH*WW)            // 3136
#define M_TOTAL (NN*HWSZ)       // 25088
#define KD (KKER*CIN)           // 2304

// Scratch (device globals — no runtime allocation allowed)
__device__ float g_xnhwc[(size_t)NN*HWSZ*CIN];                  // 25.7 MB
__device__ __nv_bfloat16 g_Vhi[(size_t)M_TOTAL*KD];             // 115.6 MB
__device__ __nv_bfloat16 g_Vlo[(size_t)M_TOTAL*KD];             // 115.6 MB
__device__ __nv_bfloat16 g_Bhi[(size_t)COUT*KD];                // 1.18 MB
__device__ __nv_bfloat16 g_Blo[(size_t)COUT*KD];                // 1.18 MB

// ---------------------------------------------------------------------------
// helpers
// ---------------------------------------------------------------------------
__device__ __forceinline__ uint32_t smem_u32(const void* p) {
    uint32_t a;
    asm("{ .reg .u64 t; cvta.to.shared.u64 t, %1; cvt.u32.u64 %0, t; }"
        : "=r"(a) : "l"(p));
    return a;
}
__device__ __forceinline__ void cp_async16(uint32_t saddr, const void* gptr) {
    asm volatile("cp.async.cg.shared.global [%0], [%1], 16;"
                 :: "r"(saddr), "l"(__cvta_generic_to_global(gptr)) : "memory");
}
__device__ __forceinline__ void cp_commit() {
    asm volatile("cp.async.commit_group;" ::: "memory");
}
template <int N>
__device__ __forceinline__ void cp_wait() {
    asm volatile("cp.async.wait_group %0;" :: "n"(N) : "memory");
}
__device__ __forceinline__ void ldsm4(uint32_t* d, uint32_t addr) {
    asm volatile("ldmatrix.sync.aligned.m8n8.x4.shared.b16 {%0,%1,%2,%3}, [%4];"
                 : "=r"(d[0]), "=r"(d[1]), "=r"(d[2]), "=r"(d[3]) : "r"(addr));
}
__device__ __forceinline__ void mma_bf16(float* c, const uint32_t* a, const uint32_t* b) {
    asm volatile(
        "mma.sync.aligned.m16n8k16.row.col.f32.bf16.bf16.f32 "
        "{%0,%1,%2,%3}, {%4,%5,%6,%7}, {%8,%9}, {%0,%1,%2,%3};"
        : "+f"(c[0]), "+f"(c[1]), "+f"(c[2]), "+f"(c[3])
        : "r"(a[0]), "r"(a[1]), "r"(a[2]), "r"(a[3]), "r"(b[0]), "r"(b[1]));
}
__device__ __forceinline__ void split_bf16(float v, __nv_bfloat16& hi, __nv_bfloat16& lo) {
    hi = __float2bfloat16_rn(v);
    lo = __float2bfloat16_rn(v - __bfloat162float(hi));
}

// ---------------------------------------------------------------------------
// Kernel 1: NCHW -> NHWC transpose
// ---------------------------------------------------------------------------
__global__ void k_transpose(const float* __restrict__ x) {
    __shared__ float t[32][33];
    int n   = blockIdx.z;
    int hw0 = blockIdx.x * 32;
    int c0  = blockIdx.y * 32;
    int tx = threadIdx.x, ty = threadIdx.y;
    const float* xin = x + (size_t)n * CIN * HWSZ;
    #pragma unroll
    for (int i = 0; i < 4; i++) {
        int c = c0 + ty + i * 8;
        t[ty + i * 8][tx] = xin[(size_t)c * HWSZ + hw0 + tx];
    }
    __syncthreads();
    float* xo = g_xnhwc + (size_t)n * HWSZ * CIN;
    #pragma unroll
    for (int i = 0; i < 4; i++) {
        int hw = hw0 + ty + i * 8;
        xo[(size_t)hw * CIN + c0 + tx] = t[tx][ty + i * 8];
    }
}

// ---------------------------------------------------------------------------
// Kernel 2: weight -> B[co][ker*256+ci], split bf16 hi/lo
// ---------------------------------------------------------------------------
__global__ void k_wt(const float* __restrict__ w) {
    int idx = blockIdx.x * 256 + threadIdx.x;   // COUT*KD
    int kk = idx % KD;
    int co = idx / KD;
    int ker = kk >> 8;
    int ci  = kk & 255;
    float v = w[((size_t)co * CIN + ci) * KKER + ker];
    __nv_bfloat16 hi, lo;
    split_bf16(v, hi, lo);
    g_Bhi[idx] = hi;
    g_Blo[idx] = lo;
}

// ---------------------------------------------------------------------------
// Kernel 3: bilinear gather + modulation -> V[m][ker*256+c], split bf16
// ---------------------------------------------------------------------------
__global__ __launch_bounds__(256) void k_gather(const float* __restrict__ offset,
                                                const float* __restrict__ mask) {
    int pix = blockIdx.x;
    int c   = threadIdx.x;
    int n   = pix / HWSZ;
    int hw  = pix % HWSZ;
    int ho  = hw / WW, wo = hw % WW;
    const float* xb = g_xnhwc + (size_t)n * HWSZ * CIN;
    size_t vbase = (size_t)pix * KD;

    #pragma unroll
    for (int k = 0; k < KKER; k++) {
        float dy = offset[((size_t)n * 18 + 2 * k)     * HWSZ + hw];
        float dx = offset[((size_t)n * 18 + 2 * k + 1) * HWSZ + hw];
        float mm = mask  [((size_t)n * KKER + k)       * HWSZ + hw];
        float py = dy + (float)(k / 3) + (float)(ho - 1);
        float px = dx + (float)(k % 3) + (float)(wo - 1);
        float fy = floorf(py), fx = floorf(px);
        int y0 = (int)fy, x0 = (int)fx;
        float wy1 = py - fy, wx1 = px - fx;
        float wy0 = 1.0f - wy1, wx0 = 1.0f - wx1;

        float acc = 0.0f;
        if (y0 >= 0 && y0 < HH && x0 >= 0 && x0 < WW)
            acc += (wy0 * wx0) * xb[(size_t)(y0 * WW + x0) * CIN + c];
        if (y0 >= 0 && y0 < HH && x0 + 1 < WW && x0 + 1 >= 0)
            acc += (wy0 * wx1) * xb[(size_t)(y0 * WW + x0 + 1) * CIN + c];
        if (y0 + 1 >= 0 && y0 + 1 < HH && x0 >= 0 && x0 < WW)
            acc += (wy1 * wx0) * xb[(size_t)((y0 + 1) * WW + x0) * CIN + c];
        if (y0 + 1 < HH && y0 + 1 >= 0 && x0 + 1 < WW && x0 + 1 >= 0)
            acc += (wy1 * wx1) * xb[(size_t)((y0 + 1) * WW + x0 + 1) * CIN + c];
        acc *= mm;
        __nv_bfloat16 hi, lo;
        split_bf16(acc, hi, lo);
        g_Vhi[vbase + k * CIN + c] = hi;
        g_Vlo[vbase + k * CIN + c] = lo;
    }
}

// ---------------------------------------------------------------------------
// Kernel 4: split-bf16 HMMA GEMM  C[25088,256] = V * B^T  (+bias)
// BM=128 BN=64 BK=32, 3-stage cp.async, 8 warps (4x2), warp tile 32x32.
// smem rows padded to 80B (5x16B chunks): ldmatrix phases 5r mod 8 distinct.
// ---------------------------------------------------------------------------
#define BK 32
#define NCHUNK (KD / BK)        // 72
#define ROWB 80                 // bytes per smem row (32 bf16 = 64B data + 16B pad)
#define A_TILE (128 * ROWB)     // 10240
#define B_TILE (64 * ROWB)      // 5120
#define STAGE_BYTES (2 * A_TILE + 2 * B_TILE)   // 30720
#define OFF_AHI 0
#define OFF_ALO A_TILE
#define OFF_BHI (2 * A_TILE)
#define OFF_BLO (2 * A_TILE + B_TILE)
#define SMEM_TOTAL (3 * STAGE_BYTES)            // 92160

__global__ __launch_bounds__(256) void k_gemm_mma(const float* __restrict__ bias,
                                                  float* __restrict__ out) {
    extern __shared__ char smem[];
    uint32_t sbase = smem_u32(smem);
    int tid  = threadIdx.x;
    int lane = tid & 31;
    int wid  = tid >> 5;
    int wm   = wid & 3;         // 0..3  (M)
    int wn   = wid >> 2;        // 0..1  (N)
    int n0 = blockIdx.x * 64;
    int m0 = blockIdx.y * 128;

    const __nv_bfloat16* Ahi_g = g_Vhi + (size_t)m0 * KD;
    const __nv_bfloat16* Alo_g = g_Vlo + (size_t)m0 * KD;
    const __nv_bfloat16* Bhi_g = g_Bhi + (size_t)n0 * KD;
    const __nv_bfloat16* Blo_g = g_Blo + (size_t)n0 * KD;

    // per-thread cp.async coordinates
    int a_row0 = tid >> 2;            // + 64 for second
    int a_c    = tid & 3;
    int b_row  = tid >> 2;            // 0..63
    int b_c    = tid & 3;

    auto issue = [&](int buf, int kt) {
        uint32_t sb = sbase + buf * STAGE_BYTES;
        int kel = kt * BK;
        #pragma unroll
        for (int r = 0; r < 2; r++) {
            int row = a_row0 + r * 64;
            uint32_t d = sb + OFF_AHI + row * ROWB + a_c * 16;
            cp_async16(d, Ahi_g + (size_t)row * KD + kel + a_c * 8);
            d = sb + OFF_ALO + row * ROWB + a_c * 16;
            cp_async16(d, Alo_g + (size_t)row * KD + kel + a_c * 8);
        }
        {
            uint32_t d = sb + OFF_BHI + b_row * ROWB + b_c * 16;
            cp_async16(d, Bhi_g + (size_t)b_row * KD + kel + b_c * 8);
            d = sb + OFF_BLO + b_row * ROWB + b_c * 16;
            cp_async16(d, Blo_g + (size_t)b_row * KD + kel + b_c * 8);
        }
    };

    float acc[2][4][4];
    #pragma unroll
    for (int i = 0; i < 2; i++)
        #pragma unroll
        for (int j = 0; j < 4; j++)
            #pragma unroll
            for (int r = 0; r < 4; r++) acc[i][j][r] = 0.0f;

    // ldmatrix addresses (byte offsets within a tile)
    int a_lrow = (lane & 7) + ((lane >> 3) & 1) * 8;   // + mt*16 + wm*32
    int a_lc   = (lane >> 4) & 1;                      // + 2*ks
    int b_lrow = (lane & 7) + ((lane >> 4) & 1) * 8;   // + p*16 + wn*32
    int b_lc   = (lane >> 3) & 1;                      // + 2*ks

    issue(0, 0); cp_commit();
    issue(1, 1); cp_commit();

    for (int kt = 0; kt < NCHUNK; kt++) {
        cp_wait<1>();
        __syncthreads();
        if (kt + 2 < NCHUNK) issue((kt + 2) % 3, kt + 2);
        cp_commit();

        uint32_t sb = sbase + (kt % 3) * STAGE_BYTES;
        #pragma unroll
        for (int ks = 0; ks < 2; ks++) {
            uint32_t Ah[2][4], Al[2][4], Bh[2][4], Bl[2][4];
            #pragma unroll
            for (int mt = 0; mt < 2; mt++) {
                int row = wm * 32 + mt * 16 + a_lrow;
                int c   = 2 * ks + a_lc;
                ldsm4(Ah[mt], sb + OFF_AHI + row * ROWB + c * 16);
                ldsm4(Al[mt], sb + OFF_ALO + row * ROWB + c * 16);
            }
            #pragma unroll
            for (int p = 0; p < 2; p++) {
                int row = wn * 32 + p * 16 + b_lrow;
                int c   = 2 * ks + b_lc;
                ldsm4(Bh[p], sb + OFF_BHI + row * ROWB + c * 16);
                ldsm4(Bl[p], sb + OFF_BLO + row * ROWB + c * 16);
            }
            #pragma unroll
            for (int mt = 0; mt < 2; mt++) {
                #pragma unroll
                for (int nt = 0; nt < 4; nt++) {
                    int p = nt >> 1;
                    const uint32_t* bh = &Bh[p][(nt & 1) * 2];
                    const uint32_t* bl = &Bl[p][(nt & 1) * 2];
                    mma_bf16(acc[mt][nt], Ah[mt], bh);
                    mma_bf16(acc[mt][nt], Ah[mt], bl);
                    mma_bf16(acc[mt][nt], Al[mt], bh);
                }
            }
        }
    }

    // epilogue: transpose through smem -> coalesced NCHW writes
    __syncthreads();
    float* ep = reinterpret_cast<float*>(smem);   // [64 co][132 m]
    #pragma unroll
    for (int mt = 0; mt < 2; mt++) {
        #pragma unroll
        for (int nt = 0; nt < 4; nt++) {
            #pragma unroll
            for (int r = 0; r < 4; r++) {
                int m_l  = wm * 32 + mt * 16 + (lane >> 2) + ((r >> 1) ? 8 : 0);
                int co_l = wn * 32 + nt * 8 + (lane & 3) * 2 + (r & 1);
                ep[co_l * 132 + m_l] = acc[mt][nt][r];
            }
        }
    }
    __syncthreads();
    #pragma unroll
    for (int it = 0; it < 8; it++) {
        int idx = tid + it * 256;     // 0..2047
        int co  = idx >> 5;
        int m_l = (idx & 31) * 4;
        float4 v = *reinterpret_cast<float4*>(&ep[co * 132 + m_l]);
        float bv = bias[n0 + co];
        v.x += bv; v.y += bv; v.z += bv; v.w += bv;
        int mg = m0 + m_l;
        int n_img = mg / HWSZ;
        int hw = mg - n_img * HWSZ;
        float* op = out + ((size_t)n_img * COUT + n0 + co) * HWSZ + hw;
        *reinterpret_cast<float4*>(op) = v;
    }
}

// ---------------------------------------------------------------------------
// Launch
// ---------------------------------------------------------------------------
extern "C" void kernel_launch(void* const* d_in, const int* in_sizes, int n_in,
                              void* d_out, int out_size) {
    const float* x      = (const float*)d_in[0];
    const float* offset = (const float*)d_in[1];
    const float* mask   = (const float*)d_in[2];
    const float* weight = (const float*)d_in[3];
    const float* bias   = (const float*)d_in[4];
    float* out = (float*)d_out;

    {
        dim3 grid(HWSZ / 32, CIN / 32, NN);
        dim3 block(32, 8);
        k_transpose<<<grid, block>>>(x);
    }
    k_wt<<<KD, 256>>>(weight);
    k_gather<<<M_TOTAL, 256>>>(offset, mask);
    {
        static bool attr_set = false;
        if (!attr_set) {
            cudaFuncSetAttribute(k_gemm_mma,
                                 cudaFuncAttributeMaxDynamicSharedMemorySize,
                                 SMEM_TOTAL);
            attr_set = true;
        }
        dim3 grid(COUT / 64, M_TOTAL / 128);   // 4 x 196
        k_gemm_mma<<<grid, 256, SMEM_TOTAL>>>(bias, out);
    }
}